// round 1
// baseline (speedup 1.0000x reference)
#include <cuda_runtime.h>
#include <math.h>

#define NT 16384
#define HID 1024
#define NH 512
#define G3 1536
#define SCAN_CTAS 16

// ---------------- scratch (device globals; no allocation) ----------------
__device__ __align__(16) float d_xn[16384 * 1024];   // layernormed x
__device__ __align__(16) float d_ig[16384 * 1536];   // igates
__device__ __align__(16) float d_hs[16384 * 512];    // h trajectory
__device__ __align__(16) float d_g[16384 * 512];     // gelu(hs)
__device__ __align__(16) float d_y1[16384 * 1024];
__device__ __align__(16) float d_y2[16384 * 1024];

__device__ __align__(16) float g_hbuf[2][NH];
__device__ unsigned long long g_tickets;             // monotonic ticket barrier

// ---------------- small helpers ----------------
__device__ __forceinline__ unsigned long long ld_acq(const unsigned long long* p) {
    unsigned long long v;
    asm volatile("ld.acquire.gpu.u64 %0, [%1];" : "=l"(v) : "l"(p) : "memory");
    return v;
}
__device__ __forceinline__ void ffma2(unsigned long long& d, unsigned long long a, unsigned long long b) {
    asm volatile("fma.rn.f32x2 %0, %1, %2, %0;" : "+l"(d) : "l"(a), "l"(b));
}
__device__ __forceinline__ unsigned long long pk2(float lo, float hi) {
    unsigned long long r;
    asm("mov.b64 %0, {%1, %2};" : "=l"(r) : "f"(lo), "f"(hi));
    return r;
}
__device__ __forceinline__ float2 up2(unsigned long long v) {
    float lo, hi;
    asm("mov.b64 {%0, %1}, %2;" : "=f"(lo), "=f"(hi) : "l"(v));
    return make_float2(lo, hi);
}
__device__ __forceinline__ float sigmoid_acc(float x) { return 1.0f / (1.0f + expf(-x)); }

// ---------------- LayerNorm ----------------
__global__ __launch_bounds__(256) void ln_kernel(const float* __restrict__ x,
                                                 const float* __restrict__ w,
                                                 const float* __restrict__ bb,
                                                 float* __restrict__ xn) {
    const int row = blockIdx.x;
    const int tid = threadIdx.x;
    const float4 v = ((const float4*)(x + (size_t)row * HID))[tid];
    float s = v.x + v.y + v.z + v.w;
    float q = v.x * v.x + v.y * v.y + v.z * v.z + v.w * v.w;
#pragma unroll
    for (int off = 16; off; off >>= 1) {
        s += __shfl_xor_sync(0xffffffffu, s, off);
        q += __shfl_xor_sync(0xffffffffu, q, off);
    }
    __shared__ float rs[8], rq[8];
    __shared__ float mu_s, rstd_s;
    const int wid = tid >> 5, lane = tid & 31;
    if (lane == 0) { rs[wid] = s; rq[wid] = q; }
    __syncthreads();
    if (tid == 0) {
        float S = 0.f, Q = 0.f;
#pragma unroll
        for (int i = 0; i < 8; i++) { S += rs[i]; Q += rq[i]; }
        float mu = S * (1.0f / HID);
        float var = Q * (1.0f / HID) - mu * mu;
        mu_s = mu;
        rstd_s = rsqrtf(var + 1e-5f);
    }
    __syncthreads();
    const float mu = mu_s, rstd = rstd_s;
    const float4 wv = ((const float4*)w)[tid];
    const float4 bv = ((const float4*)bb)[tid];
    float4 o;
    o.x = (v.x - mu) * rstd * wv.x + bv.x;
    o.y = (v.y - mu) * rstd * wv.y + bv.y;
    o.z = (v.z - mu) * rstd * wv.z + bv.z;
    o.w = (v.w - mu) * rstd * wv.w + bv.w;
    ((float4*)(xn + (size_t)row * HID))[tid] = o;
}

// ---------------- SGEMM: C[M,N] = A[M,K] * B[N,K]^T + bias[N] ----------------
#define BM 128
#define BN 128
#define BKK 16
__global__ __launch_bounds__(256) void sgemm_nt(const float* __restrict__ A,
                                                const float* __restrict__ B,
                                                const float* __restrict__ bias,
                                                float* __restrict__ C,
                                                int M, int N, int K) {
    __shared__ float As[BKK][BM];
    __shared__ float Bs[BKK][BN];
    const int tid = threadIdx.x;
    const int bm = blockIdx.y, bn = blockIdx.x;
    const float* Ab = A + (size_t)bm * BM * K;
    const float* Bb = B + (size_t)bn * BN * K;
    const int lrow = tid >> 2;         // 0..63
    const int lcol = (tid & 3) << 2;   // 0,4,8,12
    const int tx = tid & 15, ty = tid >> 4;
    float acc[8][8];
#pragma unroll
    for (int i = 0; i < 8; i++)
#pragma unroll
        for (int jj = 0; jj < 8; jj++) acc[i][jj] = 0.f;

    for (int k0 = 0; k0 < K; k0 += BKK) {
        const float4 a0 = *(const float4*)(Ab + (size_t)lrow * K + k0 + lcol);
        const float4 a1 = *(const float4*)(Ab + (size_t)(lrow + 64) * K + k0 + lcol);
        const float4 b0 = *(const float4*)(Bb + (size_t)lrow * K + k0 + lcol);
        const float4 b1 = *(const float4*)(Bb + (size_t)(lrow + 64) * K + k0 + lcol);
        __syncthreads();
        As[lcol + 0][lrow] = a0.x; As[lcol + 1][lrow] = a0.y;
        As[lcol + 2][lrow] = a0.z; As[lcol + 3][lrow] = a0.w;
        As[lcol + 0][lrow + 64] = a1.x; As[lcol + 1][lrow + 64] = a1.y;
        As[lcol + 2][lrow + 64] = a1.z; As[lcol + 3][lrow + 64] = a1.w;
        Bs[lcol + 0][lrow] = b0.x; Bs[lcol + 1][lrow] = b0.y;
        Bs[lcol + 2][lrow] = b0.z; Bs[lcol + 3][lrow] = b0.w;
        Bs[lcol + 0][lrow + 64] = b1.x; Bs[lcol + 1][lrow + 64] = b1.y;
        Bs[lcol + 2][lrow + 64] = b1.z; Bs[lcol + 3][lrow + 64] = b1.w;
        __syncthreads();
#pragma unroll
        for (int k = 0; k < BKK; ++k) {
            float ar[8], br[8];
            *(float4*)&ar[0] = *(const float4*)&As[k][ty * 8];
            *(float4*)&ar[4] = *(const float4*)&As[k][ty * 8 + 4];
            *(float4*)&br[0] = *(const float4*)&Bs[k][tx * 8];
            *(float4*)&br[4] = *(const float4*)&Bs[k][tx * 8 + 4];
#pragma unroll
            for (int i = 0; i < 8; i++)
#pragma unroll
                for (int jj = 0; jj < 8; jj++) acc[i][jj] += ar[i] * br[jj];
        }
    }
#pragma unroll
    for (int i = 0; i < 8; i++) {
        const size_t row = (size_t)bm * BM + ty * 8 + i;
        float* Cr = C + row * N + bn * BN + tx * 8;
        const float* bp = bias + bn * BN + tx * 8;
#pragma unroll
        for (int jj = 0; jj < 8; jj++) Cr[jj] = acc[i][jj] + bp[jj];
    }
}

// ---------------- persistent GRU scan (16 CTAs, weights in registers) ----------------
__device__ __forceinline__ void grid_barrier() {
    __syncthreads();
    if (threadIdx.x == 0) {
        __threadfence();
        const unsigned long long t = atomicAdd(&g_tickets, 1ULL);
        const unsigned long long target = (t / SCAN_CTAS + 1ULL) * (unsigned long long)SCAN_CTAS;
        while (ld_acq(&g_tickets) < target) {}
    }
    __syncthreads();
}

__global__ __launch_bounds__(256, 1) void gru_scan(const float* __restrict__ w_hh,
                                                   const float* __restrict__ b_n,
                                                   const float* __restrict__ igates,
                                                   float* __restrict__ hs,
                                                   float* h_final) {
    const int c = blockIdx.x, tid = threadIdx.x;
    const int gidx = tid >> 3, li = tid & 7;
    const int j = c * 32 + gidx;

    // preload weight slice into registers: rows (j, 512+j, 1024+j), cols li*4 + m*32 + {0..3}
    unsigned long long wr[32], wz[32], wn[32];
    {
        const float* br_ = w_hh + (size_t)j * NH + li * 4;
        const float* bz_ = w_hh + (size_t)(NH + j) * NH + li * 4;
        const float* bn_ = w_hh + (size_t)(2 * NH + j) * NH + li * 4;
#pragma unroll
        for (int m = 0; m < 16; m++) {
            float4 v = *(const float4*)(br_ + m * 32);
            wr[2 * m] = pk2(v.x, v.y); wr[2 * m + 1] = pk2(v.z, v.w);
            v = *(const float4*)(bz_ + m * 32);
            wz[2 * m] = pk2(v.x, v.y); wz[2 * m + 1] = pk2(v.z, v.w);
            v = *(const float4*)(bn_ + m * 32);
            wn[2 * m] = pk2(v.x, v.y); wn[2 * m + 1] = pk2(v.z, v.w);
        }
    }
    const float bnj = b_n[j];
    if (li == 0) __stcg(&g_hbuf[0][j], 0.0f);

    float igr = 0.f, igz = 0.f, ign = 0.f;
    if (li == 0) {
        igr = igates[j];
        igz = igates[NH + j];
        ign = igates[2 * NH + j];
    }

    __shared__ __align__(16) float shh[NH];

    grid_barrier();  // h_buf[0] zeroed + visible everywhere

    for (int t = 0; t < NT; ++t) {
        const int rb = t & 1, wb = rb ^ 1;
        // stage broadcast h into SMEM (bypassing L1: written by other SMs)
        ((unsigned long long*)shh)[tid] =
            __ldcg(&((const unsigned long long*)g_hbuf[rb])[tid]);
        __syncthreads();

        unsigned long long ar = 0ULL, az = 0ULL, an = 0ULL;  // pk2(0,0) == 0
        const ulonglong2* hv2 = (const ulonglong2*)shh;
#pragma unroll
        for (int m = 0; m < 16; m++) {
            const ulonglong2 h2 = hv2[li + 8 * m];
            ffma2(ar, wr[2 * m], h2.x); ffma2(ar, wr[2 * m + 1], h2.y);
            ffma2(az, wz[2 * m], h2.x); ffma2(az, wz[2 * m + 1], h2.y);
            ffma2(an, wn[2 * m], h2.x); ffma2(an, wn[2 * m + 1], h2.y);
        }
        float2 f;
        f = up2(ar); float sr = f.x + f.y;
        f = up2(az); float sz = f.x + f.y;
        f = up2(an); float sn = f.x + f.y;
#pragma unroll
        for (int off = 4; off; off >>= 1) {
            sr += __shfl_xor_sync(0xffffffffu, sr, off);
            sz += __shfl_xor_sync(0xffffffffu, sz, off);
            sn += __shfl_xor_sync(0xffffffffu, sn, off);
        }
        if (li == 0) {
            const float r = sigmoid_acc(igr + sr);
            const float z = sigmoid_acc(igz + sz);
            const float n = tanhf(ign + r * (sn + bnj));
            const float hprev = shh[j];
            const float hnew = n + z * (hprev - n);
            __stcg(&g_hbuf[wb][j], hnew);
            hs[(size_t)t * NH + j] = hnew;
            if (h_final != nullptr && t == NT - 1) h_final[j] = hnew;
            // prefetch next step's input gates (overlaps with barrier wait)
            const int tn = (t + 1 < NT) ? (t + 1) : t;
            const float* igp = igates + (size_t)tn * G3;
            igr = igp[j]; igz = igp[NH + j]; ign = igp[2 * NH + j];
        }
        grid_barrier();
    }
}

// ---------------- gelu (tanh approx, matches jax default) ----------------
__global__ __launch_bounds__(256) void gelu_kernel(const float* __restrict__ in,
                                                   float* __restrict__ outp) {
    const size_t i = (size_t)blockIdx.x * 256 + threadIdx.x;
    const float4 v = ((const float4*)in)[i];
    const float c0 = 0.7978845608028654f, c1 = 0.044715f;
    float4 o;
    o.x = 0.5f * v.x * (1.0f + tanhf(c0 * (v.x + c1 * v.x * v.x * v.x)));
    o.y = 0.5f * v.y * (1.0f + tanhf(c0 * (v.y + c1 * v.y * v.y * v.y)));
    o.z = 0.5f * v.z * (1.0f + tanhf(c0 * (v.z + c1 * v.z * v.z * v.z)));
    o.w = 0.5f * v.w * (1.0f + tanhf(c0 * (v.w + c1 * v.w * v.w * v.w)));
    ((float4*)outp)[i] = o;
}

// ---------------- final combine: out = x + y1 * sigmoid(y2) ----------------
__global__ __launch_bounds__(256) void combine_kernel(const float* __restrict__ x,
                                                      const float* __restrict__ y1,
                                                      const float* __restrict__ y2,
                                                      float* __restrict__ outp) {
    const size_t i = (size_t)blockIdx.x * 256 + threadIdx.x;
    const float4 xv = ((const float4*)x)[i];
    const float4 a = ((const float4*)y1)[i];
    const float4 s = ((const float4*)y2)[i];
    float4 o;
    o.x = xv.x + a.x * sigmoid_acc(s.x);
    o.y = xv.y + a.y * sigmoid_acc(s.y);
    o.z = xv.z + a.z * sigmoid_acc(s.z);
    o.w = xv.w + a.w * sigmoid_acc(s.w);
    ((float4*)outp)[i] = o;
}

// ---------------- launch ----------------
extern "C" void kernel_launch(void* const* d_in, const int* in_sizes, int n_in,
                              void* d_out, int out_size) {
    const float* x     = (const float*)d_in[0];
    const float* w_ih  = (const float*)d_in[1];
    const float* w_hh  = (const float*)d_in[2];
    const float* b     = (const float*)d_in[3];
    const float* b_n   = (const float*)d_in[4];
    const float* out_w  = (const float*)d_in[5];
    const float* out_b  = (const float*)d_in[6];
    const float* out2_w = (const float*)d_in[7];
    const float* out2_b = (const float*)d_in[8];
    const float* ln_w  = (const float*)d_in[9];
    const float* ln_b  = (const float*)d_in[10];

    float* outp = (float*)d_out;
    float* hfin = nullptr;
    float* ybase = outp;
    if (out_size == 512 + 16384 * 1024) {  // tuple (h_final, y) flattened
        hfin = outp;
        ybase = outp + 512;
    }

    void *p_xn, *p_ig, *p_hs, *p_g, *p_y1, *p_y2;
    cudaGetSymbolAddress(&p_xn, d_xn);
    cudaGetSymbolAddress(&p_ig, d_ig);
    cudaGetSymbolAddress(&p_hs, d_hs);
    cudaGetSymbolAddress(&p_g, d_g);
    cudaGetSymbolAddress(&p_y1, d_y1);
    cudaGetSymbolAddress(&p_y2, d_y2);

    ln_kernel<<<NT, 256>>>(x, ln_w, ln_b, (float*)p_xn);
    sgemm_nt<<<dim3(G3 / BN, NT / BM), 256>>>((const float*)p_xn, w_ih, b,
                                              (float*)p_ig, NT, G3, HID);
    gru_scan<<<SCAN_CTAS, 256>>>(w_hh, b_n, (const float*)p_ig, (float*)p_hs, hfin);
    gelu_kernel<<<(NT * NH) / (4 * 256), 256>>>((const float*)p_hs, (float*)p_g);
    sgemm_nt<<<dim3(HID / BN, NT / BM), 256>>>((const float*)p_g, out_w, out_b,
                                               (float*)p_y1, NT, HID, NH);
    sgemm_nt<<<dim3(HID / BN, NT / BM), 256>>>((const float*)p_g, out2_w, out2_b,
                                               (float*)p_y2, NT, HID, NH);
    combine_kernel<<<(NT * HID) / (4 * 256), 256>>>(x, (const float*)p_y1,
                                                    (const float*)p_y2, ybase);
}